// round 2
// baseline (speedup 1.0000x reference)
#include <cuda_runtime.h>

#define BB 4
#define NT 2048
#define DD 512
#define HH 8
#define DHH 64
#define INNER 512
#define QKVC 1536
#define ATT_SCALE 0.125f

// Scratch (device globals — no cudaMalloc allowed)
static __device__ float g_qkv[(size_t)BB * NT * QKVC];   // 50.3 MB
static __device__ float g_obuf[(size_t)BB * NT * INNER]; // 16.8 MB

// swizzle at float4 granularity: varies with d/4 over 8 values (bank-spread)
#define SW(d) ((((d) >> 2) & 7) << 2)

// ---------------------------------------------------------------------------
// Generic tiled SGEMM: C[M,Ncols] = A[M,K] @ Bm[K,Ncols] (+ bias per column)
// 64x64 tile, K-step 16, 256 threads, 4x4 register micro-tile per thread.
// ---------------------------------------------------------------------------
template <bool HAS_BIAS>
__global__ __launch_bounds__(256) void sgemm_kernel(
    const float* __restrict__ A, const float* __restrict__ Bm,
    const float* __restrict__ bias, float* __restrict__ C,
    int M, int Ncols, int K)
{
    __shared__ float As[16][68];
    __shared__ float Bs[16][68];
    const int tid = threadIdx.x;
    const int tx = tid & 15, ty = tid >> 4;
    const int m0 = blockIdx.y << 6, n0 = blockIdx.x << 6;
    const int ar = tid >> 2, ac4 = (tid & 3) << 2;
    const int bkr = tid >> 4, bc = (tid & 15) << 2;

    float acc[4][4] = {};

    for (int k0 = 0; k0 < K; k0 += 16) {
        float4 a = *(const float4*)(A + (size_t)(m0 + ar) * K + (k0 + ac4));
        As[ac4 + 0][ar] = a.x;
        As[ac4 + 1][ar] = a.y;
        As[ac4 + 2][ar] = a.z;
        As[ac4 + 3][ar] = a.w;
        *(float4*)&Bs[bkr][bc] =
            *(const float4*)(Bm + (size_t)(k0 + bkr) * Ncols + (n0 + bc));
        __syncthreads();
#pragma unroll
        for (int kk = 0; kk < 16; kk++) {
            float av[4], bv[4];
            *(float4*)av = *(const float4*)&As[kk][ty << 2];
            *(float4*)bv = *(const float4*)&Bs[kk][tx << 2];
#pragma unroll
            for (int i = 0; i < 4; i++)
#pragma unroll
                for (int j = 0; j < 4; j++)
                    acc[i][j] = fmaf(av[i], bv[j], acc[i][j]);
        }
        __syncthreads();
    }

    float4 bv4 = make_float4(0.f, 0.f, 0.f, 0.f);
    if (HAS_BIAS) bv4 = *(const float4*)(bias + n0 + (tx << 2));
#pragma unroll
    for (int i = 0; i < 4; i++) {
        float4 o;
        o.x = acc[i][0] + bv4.x;
        o.y = acc[i][1] + bv4.y;
        o.z = acc[i][2] + bv4.z;
        o.w = acc[i][3] + bv4.w;
        *(float4*)(C + (size_t)(m0 + (ty << 2) + i) * Ncols + n0 + (tx << 2)) = o;
    }
}

// ---------------------------------------------------------------------------
// Fused flash attention with inline conv-bias from centroid_delta.
// One block per (b, h, 64-row i-tile). 256 threads.
// Thread (ty,tx) owns rows ty*4..+3 (softmax state) and d-cols tx*4..+3 (acc).
// ---------------------------------------------------------------------------
__global__ __launch_bounds__(256) void attn_kernel(
    const float* __restrict__ qkv, const float* __restrict__ cd,
    const float* __restrict__ rel_w, const float* __restrict__ rel_b,
    float* __restrict__ obuf)
{
    extern __shared__ float smem[];
    float* QsT = smem;                 // [64 d][64 i]  (swizzled)
    float* KsT = smem + 4096;          // [64 d][64 j]  (swizzled)
    float* Vs  = smem + 8192;          // [64 j][68]    (natural)
    float* Ps  = smem + 8192 + 64*68;  // [64 i][68]

    const int tid = threadIdx.x;
    const int tx = tid & 15, ty = tid >> 4;
    const int h  = blockIdx.x & 7;           // h varies fastest -> cd L2 reuse
    const int i0 = (blockIdx.x >> 3) << 6;
    const int b  = blockIdx.y;

    const float w0 = rel_w[h * 3 + 0], w1 = rel_w[h * 3 + 1], w2 = rel_w[h * 3 + 2];
    const float rb = rel_b[h];

    const size_t NN2 = (size_t)NT * NT;
    const float* cd0 = cd + (size_t)b * 3 * NN2;
    const float* cd1 = cd0 + NN2;
    const float* cd2 = cd0 + 2 * NN2;

    // Load Q tile transposed + swizzled
    {
        const int d4 = tx << 2;
#pragma unroll
        for (int it = 0; it < 4; it++) {
            int i = ty + (it << 4);
            float4 v = *(const float4*)(qkv + ((size_t)b * NT + i0 + i) * QKVC + h * DHH + d4);
            QsT[(d4 + 0) * 64 + (i ^ SW(d4 + 0))] = v.x;
            QsT[(d4 + 1) * 64 + (i ^ SW(d4 + 1))] = v.y;
            QsT[(d4 + 2) * 64 + (i ^ SW(d4 + 2))] = v.z;
            QsT[(d4 + 3) * 64 + (i ^ SW(d4 + 3))] = v.w;
        }
    }

    float m_r[4], l_r[4], acc[4][4];
#pragma unroll
    for (int i = 0; i < 4; i++) {
        m_r[i] = -1e30f;
        l_r[i] = 0.f;
        acc[i][0] = acc[i][1] = acc[i][2] = acc[i][3] = 0.f;
    }

    for (int j0 = 0; j0 < NT; j0 += 64) {
        __syncthreads();  // previous PV done before overwriting K/V/P
        // Load K (transposed+swizzled) and V (natural) tiles
        {
            const int d4 = tx << 2;
#pragma unroll
            for (int it = 0; it < 4; it++) {
                int j = ty + (it << 4);
                const float* base = qkv + ((size_t)b * NT + j0 + j) * QKVC;
                float4 kv = *(const float4*)(base + INNER + h * DHH + d4);
                KsT[(d4 + 0) * 64 + (j ^ SW(d4 + 0))] = kv.x;
                KsT[(d4 + 1) * 64 + (j ^ SW(d4 + 1))] = kv.y;
                KsT[(d4 + 2) * 64 + (j ^ SW(d4 + 2))] = kv.z;
                KsT[(d4 + 3) * 64 + (j ^ SW(d4 + 3))] = kv.w;
                float4 vv = *(const float4*)(base + 2 * INNER + h * DHH + d4);
                *(float4*)&Vs[j * 68 + d4] = vv;
            }
        }
        __syncthreads();

        // S = Q K^T  (4x4 micro-tile per thread; 8 LDS.128 per 64 FMA)
        float s[4][4];
#pragma unroll
        for (int i = 0; i < 4; i++)
            s[i][0] = s[i][1] = s[i][2] = s[i][3] = 0.f;
#pragma unroll 4
        for (int d = 0; d < 64; d += 4) {
#pragma unroll
            for (int k = 0; k < 4; k++) {
                float av[4], bv[4];
                *(float4*)av = *(const float4*)&QsT[(d + k) * 64 + ((ty << 2) ^ SW(d + k))];
                *(float4*)bv = *(const float4*)&KsT[(d + k) * 64 + ((tx << 2) ^ SW(d + k))];
#pragma unroll
                for (int i = 0; i < 4; i++)
#pragma unroll
                    for (int j = 0; j < 4; j++)
                        s[i][j] = fmaf(av[i], bv[j], s[i][j]);
            }
        }

        // scale + conv1x1 bias (coalesced float4 cd reads)
#pragma unroll
        for (int i = 0; i < 4; i++) {
            size_t ro = (size_t)(i0 + (ty << 2) + i) * NT + j0 + (tx << 2);
            float4 c0 = *(const float4*)(cd0 + ro);
            float4 c1 = *(const float4*)(cd1 + ro);
            float4 c2 = *(const float4*)(cd2 + ro);
            s[i][0] = fmaf(s[i][0], ATT_SCALE, w0 * c0.x + w1 * c1.x + w2 * c2.x + rb);
            s[i][1] = fmaf(s[i][1], ATT_SCALE, w0 * c0.y + w1 * c1.y + w2 * c2.y + rb);
            s[i][2] = fmaf(s[i][2], ATT_SCALE, w0 * c0.z + w1 * c1.z + w2 * c2.z + rb);
            s[i][3] = fmaf(s[i][3], ATT_SCALE, w0 * c0.w + w1 * c1.w + w2 * c2.w + rb);
        }

        // online softmax (row stats reduced over the 16-lane tx group)
#pragma unroll
        for (int i = 0; i < 4; i++) {
            float mx = fmaxf(fmaxf(s[i][0], s[i][1]), fmaxf(s[i][2], s[i][3]));
#pragma unroll
            for (int off = 8; off > 0; off >>= 1)
                mx = fmaxf(mx, __shfl_xor_sync(0xffffffffu, mx, off));
            float mnew = fmaxf(m_r[i], mx);
            float fac = __expf(m_r[i] - mnew);
            m_r[i] = mnew;
            float p0 = __expf(s[i][0] - mnew);
            float p1 = __expf(s[i][1] - mnew);
            float p2 = __expf(s[i][2] - mnew);
            float p3 = __expf(s[i][3] - mnew);
            float rs = (p0 + p1) + (p2 + p3);
#pragma unroll
            for (int off = 8; off > 0; off >>= 1)
                rs += __shfl_xor_sync(0xffffffffu, rs, off);
            l_r[i] = l_r[i] * fac + rs;
            acc[i][0] *= fac; acc[i][1] *= fac; acc[i][2] *= fac; acc[i][3] *= fac;
            *(float4*)&Ps[((ty << 2) + i) * 68 + (tx << 2)] = make_float4(p0, p1, p2, p3);
        }
        __syncthreads();

        // O += P V  (p-reads broadcast, v-reads conflict-free float4)
#pragma unroll 4
        for (int jb = 0; jb < 64; jb += 4) {
            float pr[4][4];
#pragma unroll
            for (int i = 0; i < 4; i++)
                *(float4*)pr[i] = *(const float4*)&Ps[((ty << 2) + i) * 68 + jb];
#pragma unroll
            for (int k = 0; k < 4; k++) {
                float4 v = *(const float4*)&Vs[(jb + k) * 68 + (tx << 2)];
#pragma unroll
                for (int i = 0; i < 4; i++) {
                    acc[i][0] = fmaf(pr[i][k], v.x, acc[i][0]);
                    acc[i][1] = fmaf(pr[i][k], v.y, acc[i][1]);
                    acc[i][2] = fmaf(pr[i][k], v.z, acc[i][2]);
                    acc[i][3] = fmaf(pr[i][k], v.w, acc[i][3]);
                }
            }
        }
    }

    // Normalize and write O into [B, N, h*64+d] layout for the output GEMM
#pragma unroll
    for (int i = 0; i < 4; i++) {
        float inv = 1.0f / l_r[i];
        float4 o = make_float4(acc[i][0] * inv, acc[i][1] * inv,
                               acc[i][2] * inv, acc[i][3] * inv);
        *(float4*)(obuf + ((size_t)b * NT + i0 + (ty << 2) + i) * INNER + h * DHH + (tx << 2)) = o;
    }
}

// ---------------------------------------------------------------------------
extern "C" void kernel_launch(void* const* d_in, const int* in_sizes, int n_in,
                              void* d_out, int out_size)
{
    const float* x     = (const float*)d_in[0];
    const float* cd    = (const float*)d_in[1];
    const float* Wqkv  = (const float*)d_in[2];
    const float* Wout  = (const float*)d_in[3];
    const float* bout  = (const float*)d_in[4];
    const float* rel_w = (const float*)d_in[5];
    const float* rel_b = (const float*)d_in[6];
    float* out = (float*)d_out;

    float *qkvb = nullptr, *obuf = nullptr;
    cudaGetSymbolAddress((void**)&qkvb, g_qkv);
    cudaGetSymbolAddress((void**)&obuf, g_obuf);

    const int ATTN_SMEM = (4096 * 2 + 64 * 68 * 2) * (int)sizeof(float);  // 67584 B
    cudaFuncSetAttribute(attn_kernel, cudaFuncAttributeMaxDynamicSharedMemorySize,
                         ATTN_SMEM);

    dim3 blk(256);
    // qkv = x @ Wqkv : [8192,512] x [512,1536]
    sgemm_kernel<false><<<dim3(QKVC / 64, (BB * NT) / 64), blk>>>(
        x, Wqkv, nullptr, qkvb, BB * NT, QKVC, DD);
    // fused attention (h fastest in grid.x for cd L2 reuse)
    attn_kernel<<<dim3(HH * (NT / 64), BB), blk, ATTN_SMEM>>>(
        qkvb, cd, rel_w, rel_b, obuf);
    // out = obuf @ Wout + bout : [8192,512] x [512,512]
    sgemm_kernel<true><<<dim3(DD / 64, (BB * NT) / 64), blk>>>(
        obuf, Wout, bout, out, BB * NT, DD, DD);
}